// round 4
// baseline (speedup 1.0000x reference)
#include <cuda_runtime.h>
#include <math.h>

// Problem constants (match reference)
#define BB 8
#define HH 256
#define WW 256
#define XT 4                      // x-columns per block in the column pass
#define NBLK_COL (BB * (WW / XT)) // 512
#define KWIN 4                    // column-pass window radius (exactness-checked)
#define TROWS (HH + 2 * KWIN)     // padded tile rows (264)

typedef unsigned long long u64;

// ---------------------------------------------------------------------------
// Scratch (device globals — no allocation allowed)
// g_packed[r*W+x] = d1 | (d0<<16): horizontal distance to nearest 1 / nearest 0,
// clamped to 1000 (sentinel => row-pass value 1e10, matching reference INF).
// ---------------------------------------------------------------------------
__device__ unsigned g_packed[BB * HH * WW];
__device__ double d_partials[NBLK_COL][4]; // {sum p*dist, sum p*t, sum p*p, sum t*t}
__device__ int g_cnt;

// ---------------------------------------------------------------------------
// Kernel 1: one block per image row. Ballot the row into a 256-bit mask,
// build prefix/suffix nearest-bit summaries (4x 64-bit words), then each
// thread computes its pixel's distances branchlessly. Also resets g_cnt.
// ---------------------------------------------------------------------------
__global__ __launch_bounds__(WW) void row_kernel(const float* __restrict__ target) {
    const int r = blockIdx.x;   // b*HH + y
    const int i = threadIdx.x;  // x
    if (r == 0 && i == 0) g_cnt = 0;

    __shared__ unsigned sword[8];
    __shared__ u64 sw64[4];
    __shared__ int sR1[4], sL1[4], sR0[4], sL0[4];

    const float t = target[r * WW + i];
    const unsigned bal = __ballot_sync(0xffffffffu, t > 0.5f);
    if ((i & 31) == 0) sword[i >> 5] = bal;
    __syncthreads();

    if (i == 0) {
        u64 w[4];
#pragma unroll
        for (int k = 0; k < 4; ++k) {
            w[k] = (u64)sword[2 * k] | ((u64)sword[2 * k + 1] << 32);
            sw64[k] = w[k];
        }
        int r1 = -100000, r0 = -100000;
#pragma unroll
        for (int k = 0; k < 4; ++k) {
            sR1[k] = r1; sR0[k] = r0;
            if (w[k])  r1 = 64 * k + 63 - __clzll(w[k]);
            const u64 c = ~w[k];
            if (c)     r0 = 64 * k + 63 - __clzll(c);
        }
        int l1 = 100000, l0 = 100000;
#pragma unroll
        for (int k = 3; k >= 0; --k) {
            sL1[k] = l1; sL0[k] = l0;
            if (w[k])  l1 = 64 * k + __ffsll((long long)w[k]) - 1;
            const u64 c = ~w[k];
            if (c)     l0 = 64 * k + __ffsll((long long)c) - 1;
        }
    }
    __syncthreads();

    const int wi = i >> 6, b = i & 63;
    const u64 m1 = sw64[wi];
    const u64 m0 = ~m1;
    const u64 lowsel = (2ull << b) - 1ull;      // bits 0..b (b=63 -> all ones)
    const u64 hisel  = ~((1ull << b) - 1ull);   // bits b..63

    u64 x; int p;
    // distance to nearest 1
    x = m1 & lowsel; p = x ? (64 * wi + 63 - __clzll(x)) : sR1[wi];
    int dl = i - p;
    x = m1 & hisel;  p = x ? (64 * wi + __ffsll((long long)x) - 1) : sL1[wi];
    int dr = p - i;
    const int d1 = min(min(dl, dr), 1000);
    // distance to nearest 0
    x = m0 & lowsel; p = x ? (64 * wi + 63 - __clzll(x)) : sR0[wi];
    dl = i - p;
    x = m0 & hisel;  p = x ? (64 * wi + __ffsll((long long)x) - 1) : sL0[wi];
    dr = p - i;
    const int d0 = min(min(dl, dr), 1000);

    g_packed[r * WW + i] = (unsigned)d1 | ((unsigned)d0 << 16);
}

// ---------------------------------------------------------------------------
// Kernel 2: column min-plus (windowed K=4, exactness-checked with full
// fallback) + sigmoid + dice/boundary partials + last-block finalize.
// Block = XT columns of one image; thread = y.
// ---------------------------------------------------------------------------
struct TileMem {
    float sa[TROWS][XT];
    float sb[TROWS][XT];
    float rs[8][4];
};
struct FinMem {
    double f[4][NBLK_COL];
};
union ColShared {
    TileMem a;
    FinMem  b;
};

__global__ __launch_bounds__(HH) void col_fused(const float* __restrict__ pred,
                                                const float* __restrict__ target,
                                                const int* __restrict__ fl_ptr,
                                                float* __restrict__ out) {
    const int bx = blockIdx.x;            // 0 .. NBLK_COL-1
    const int b  = bx / (WW / XT);        // batch
    const int x0 = (bx % (WW / XT)) * XT; // first x column
    const int base = b * HH * WW;

    __shared__ __align__(16) ColShared sh;

    // Build padded tile from packed row distances (coalesced-ish uint32 loads).
    for (int e = threadIdx.x; e < TROWS * XT; e += HH) {
        const int ry = e >> 2;            // XT == 4
        const int yy = ry - KWIN;
        const int xl = e & 3;
        if (yy >= 0 && yy < HH) {
            const unsigned v = g_packed[base + yy * WW + x0 + xl];
            const int d1 = (int)(v & 0xFFFFu);
            const int d0 = (int)(v >> 16);
            sh.a.sa[ry][xl] = (d1 >= 1000) ? 1e10f : (float)(d1 * d1);
            sh.a.sb[ry][xl] = (d0 >= 1000) ? 1e10f : (float)(d0 * d0);
        } else {
            sh.a.sa[ry][xl] = 1e18f;
            sh.a.sb[ry][xl] = 1e18f;
        }
    }
    __syncthreads();

    const int y = threadIdx.x;
    float aa0 = 3.0e38f, aa1 = 3.0e38f, aa2 = 3.0e38f, aa3 = 3.0e38f;
    float ab0 = 3.0e38f, ab1 = 3.0e38f, ab2 = 3.0e38f, ab3 = 3.0e38f;

#pragma unroll
    for (int dj = -KWIN; dj <= KWIN; ++dj) {
        const float d2 = (float)(dj * dj);
        const int si = y + dj + KWIN;     // always in-bounds of padded tile
        const float4 va = *reinterpret_cast<const float4*>(&sh.a.sa[si][0]);
        const float4 vb = *reinterpret_cast<const float4*>(&sh.a.sb[si][0]);
        aa0 = fminf(aa0, va.x + d2); aa1 = fminf(aa1, va.y + d2);
        aa2 = fminf(aa2, va.z + d2); aa3 = fminf(aa3, va.w + d2);
        ab0 = fminf(ab0, vb.x + d2); ab1 = fminf(ab1, vb.y + d2);
        ab2 = fminf(ab2, vb.z + d2); ab3 = fminf(ab3, vb.w + d2);
    }

    // Exactness: candidates outside the window contribute >= (K+1)^2.
    const float thresh = (float)((KWIN + 1) * (KWIN + 1));
    const float mymax = fmaxf(fmaxf(fmaxf(aa0, aa1), fmaxf(aa2, aa3)),
                              fmaxf(fmaxf(ab0, ab1), fmaxf(ab2, ab3)));
    const int need_full = __syncthreads_or(mymax > thresh);
    if (need_full) {
        aa0 = aa1 = aa2 = aa3 = 3.0e38f;
        ab0 = ab1 = ab2 = ab3 = 3.0e38f;
        float d = (float)y;
#pragma unroll 4
        for (int j = 0; j < HH; ++j) {
            const float d2 = d * d;
            d -= 1.0f;
            const float4 va = *reinterpret_cast<const float4*>(&sh.a.sa[j + KWIN][0]);
            const float4 vb = *reinterpret_cast<const float4*>(&sh.a.sb[j + KWIN][0]);
            aa0 = fminf(aa0, va.x + d2); aa1 = fminf(aa1, va.y + d2);
            aa2 = fminf(aa2, va.z + d2); aa3 = fminf(aa3, va.w + d2);
            ab0 = fminf(ab0, vb.x + d2); ab1 = fminf(ab1, vb.y + d2);
            ab2 = fminf(ab2, vb.z + d2); ab3 = fminf(ab3, vb.w + d2);
        }
    }

    // Epilogue: sigmoid(pred), dist map, per-thread partial sums.
    const int fl = *fl_ptr;
    const int gidx = base + y * WW + x0;
    const float4 pv = *reinterpret_cast<const float4*>(&pred[gidx]);
    const float4 tv = *reinterpret_cast<const float4*>(&target[gidx]);

    float pvals[XT] = {pv.x, pv.y, pv.z, pv.w};
    float tvals[XT] = {tv.x, tv.y, tv.z, tv.w};
    float ha[XT] = {aa0, aa1, aa2, aa3};
    float hb[XT] = {ab0, ab1, ab2, ab3};

    float s_pd = 0.0f, s_pt = 0.0f, s_pp = 0.0f, s_tt = 0.0f;
#pragma unroll
    for (int k = 0; k < XT; ++k) {
        float p = pvals[k];
        if (fl) p = 1.0f / (1.0f + expf(-p));
        const float dist = sqrtf(ha[k]) + sqrtf(hb[k]);
        s_pd += p * dist;
        s_pt += p * tvals[k];
        s_pp += p * p;
        s_tt += tvals[k] * tvals[k];
    }

    // Warp reduce, then combine 8 warps into doubles — fixed order.
#pragma unroll
    for (int off = 16; off > 0; off >>= 1) {
        s_pd += __shfl_down_sync(0xffffffffu, s_pd, off);
        s_pt += __shfl_down_sync(0xffffffffu, s_pt, off);
        s_pp += __shfl_down_sync(0xffffffffu, s_pp, off);
        s_tt += __shfl_down_sync(0xffffffffu, s_tt, off);
    }
    const int lane = threadIdx.x & 31;
    const int warp = threadIdx.x >> 5;
    if (lane == 0) {
        sh.a.rs[warp][0] = s_pd; sh.a.rs[warp][1] = s_pt;
        sh.a.rs[warp][2] = s_pp; sh.a.rs[warp][3] = s_tt;
    }
    __syncthreads();

    __shared__ int s_last;
    if (threadIdx.x == 0) {
        double a0 = 0.0, a1 = 0.0, a2 = 0.0, a3 = 0.0;
#pragma unroll
        for (int w = 0; w < 8; ++w) {
            a0 += (double)sh.a.rs[w][0]; a1 += (double)sh.a.rs[w][1];
            a2 += (double)sh.a.rs[w][2]; a3 += (double)sh.a.rs[w][3];
        }
        d_partials[bx][0] = a0; d_partials[bx][1] = a1;
        d_partials[bx][2] = a2; d_partials[bx][3] = a3;
        __threadfence();
        const int old = atomicAdd(&g_cnt, 1);
        s_last = (old == NBLK_COL - 1);
    }
    __syncthreads();
    if (!s_last) return;

    // -------- last block: deterministic finalize (fixed slots, fixed order) --
    __threadfence();
    const int tid = threadIdx.x;
    for (int i = tid; i < NBLK_COL; i += HH) {
        sh.b.f[0][i] = d_partials[i][0];
        sh.b.f[1][i] = d_partials[i][1];
        sh.b.f[2][i] = d_partials[i][2];
        sh.b.f[3][i] = d_partials[i][3];
    }
    __syncthreads();
    for (int off = 32; off >= 1; off >>= 1) {
        for (int i = tid; i < NBLK_COL; i += HH) {
            if ((i & 63) < off) {
                sh.b.f[0][i] += sh.b.f[0][i + off];
                sh.b.f[1][i] += sh.b.f[1][i + off];
                sh.b.f[2][i] += sh.b.f[2][i + off];
                sh.b.f[3][i] += sh.b.f[3][i + off];
            }
        }
        __syncthreads();
    }
    if (tid == 0) {
        double bl = 0.0, dl = 0.0;
        const double eps = 1e-6;
#pragma unroll
        for (int g = 0; g < BB; ++g) {
            const int s = g * 64;
            bl += sh.b.f[0][s];
            const double inter = 2.0 * sh.b.f[1][s];
            const double uni   = sh.b.f[2][s] + sh.b.f[3][s];
            dl += 1.0 - (inter + eps) / (uni + eps);
        }
        dl /= (double)BB;
        bl /= (double)(BB * HH * WW);
        out[0] = (float)(dl + bl); // ALPHA = BETA = 1
    }
}

// ---------------------------------------------------------------------------
extern "C" void kernel_launch(void* const* d_in, const int* in_sizes, int n_in,
                              void* d_out, int out_size) {
    const float* pred   = (const float*)d_in[0];
    const float* target = (const float*)d_in[1];
    const int*   fl     = (const int*)d_in[2];
    float* out = (float*)d_out;

    row_kernel<<<BB * HH, WW>>>(target);
    col_fused<<<NBLK_COL, HH>>>(pred, target, fl, out);
}

// round 5
// speedup vs baseline: 1.3191x; 1.3191x over previous
#include <cuda_runtime.h>
#include <math.h>

// Problem constants (match reference)
#define BB 8
#define HH 256
#define WW 256
#define XT 4                      // x-columns per block
#define NBLK (BB * (WW / XT))     // 512 blocks
#define KWIN 4                    // column window radius (exactness-checked)
#define TROWS (HH + 2 * KWIN)     // padded tile rows (264)

// ---------------------------------------------------------------------------
// Scratch (device globals — no allocation allowed)
// ---------------------------------------------------------------------------
__device__ unsigned g_bits[BB * HH * 8];   // bit image: 8 words per row
__device__ double d_partials[NBLK][4];     // {sum p*dist, sum p*t, sum p*p, sum t*t}
__device__ int g_bar;                      // phase barrier counter (self-resetting)
__device__ int g_fin;                      // finalize election counter (self-resetting)

// Exact distance to nearest set bit (inv=false) / clear bit (inv=true) in a
// 256-bit row, from position i. Sentinel 1000 => squared 1e10 (reference INF).
// Used only on the rare fallback path.
__device__ __forceinline__ int exact_dist(const unsigned* __restrict__ m, int i, bool inv) {
    const int wi = i >> 5, bi = i & 31;
    const unsigned mw = inv ? ~m[wi] : m[wi];
    const unsigned lowmask = (2u << bi) - 1u;     // bits 0..bi (bi=31 -> all)
    const unsigned himask  = ~((1u << bi) - 1u);  // bits bi..31
    unsigned wl = mw & lowmask;
    int dl = 100000;
    if (wl) dl = bi - (31 - __clz(wl));
    else {
        for (int k = wi - 1; k >= 0; --k) {
            const unsigned mk = inv ? ~m[k] : m[k];
            if (mk) { dl = i - (k * 32 + 31 - __clz(mk)); break; }
        }
    }
    unsigned wr = mw & himask;
    int dr = 100000;
    if (wr) dr = (__ffs(wr) - 1) - bi;
    else {
        for (int k = wi + 1; k < 8; ++k) {
            const unsigned mk = inv ? ~m[k] : m[k];
            if (mk) { dr = (k * 32 + __ffs(mk) - 1) - i; break; }
        }
    }
    return min(min(dl, dr), 1000);
}

// ---------------------------------------------------------------------------
// ONE fused kernel. 512 blocks x 256 threads, all co-resident
// (needs 4 blocks/SM; thread-capacity allows 8, smem ~8.6KB).
// Phase 0: build bit image (4 ballots/warp). Spin grid-barrier.
// Phase 1: per-block column min-plus (window K=4, exactness-checked) with
//          row-distances decoded from bits on the fly; sigmoid + partials.
// Last block (atomic election): deterministic finalize + counter reset.
// ---------------------------------------------------------------------------
__global__ __launch_bounds__(HH, 4) void fused(const float* __restrict__ pred,
                                               const float* __restrict__ target,
                                               const int* __restrict__ fl_ptr,
                                               float* __restrict__ out) {
    const int blk  = blockIdx.x;
    const int tid  = threadIdx.x;
    const int warp = tid >> 5;
    const int lane = tid & 31;

    __shared__ __align__(16) float sa[TROWS][XT];  // dist^2 to nearest 1 (clamped)
    __shared__ __align__(16) float sb[TROWS][XT];  // dist^2 to nearest 0 (clamped)
    __shared__ float rs[8][4];
    __shared__ double fg[8][2];                     // per-image {boundary, dice}
    __shared__ int s_last;

    // ---------------- Phase 0: bit image (block -> 4 rows) -----------------
    {
        const int row  = blk * 4 + (warp >> 1);   // global row in [0, B*H)
        const int half = warp & 1;
#pragma unroll
        for (int it = 0; it < 4; ++it) {
            const int px = half * 128 + it * 32 + lane;
            const float t = target[row * WW + px];
            const unsigned bal = __ballot_sync(0xffffffffu, t > 0.5f);
            if (lane == 0) g_bits[row * 8 + half * 4 + it] = bal;
        }
    }
    __syncthreads();
    if (tid == 0) {
        __threadfence();
        atomicAdd(&g_bar, 1);
        while (*(volatile int*)&g_bar < NBLK) __nanosleep(32);
        __threadfence();
    }
    __syncthreads();

    // ---------------- Phase 1: tile build from bits ------------------------
    const int b  = blk >> 6;          // image
    const int x0 = (blk & 63) * XT;   // first column
    const int base = b * HH * WW;
    const unsigned* __restrict__ rowbits = &g_bits[b * HH * 8];

    for (int ry = tid; ry < TROWS; ry += HH) {
        const int yy = ry - KWIN;
        float4 va, vb;
        if (yy >= 0 && yy < HH) {
            const unsigned* wr = rowbits + yy * 8;
            const int pos = x0 - 8;               // W bit k == row bit pos+k
            unsigned W;
            if (pos >= 0) {
                const int wi = pos >> 5, sh = pos & 31;
                const unsigned lo = wr[wi];
                const unsigned hi = (wi < 7) ? wr[wi + 1] : 0u;
                W = __funnelshift_r(lo, hi, sh);
            } else {
                W = wr[0] << (-pos);
            }
            float da[XT], db[XT];
#pragma unroll
            for (int xl = 0; xl < XT; ++xl) {
                const int x = x0 + xl;
                const unsigned win = (W >> (3 + xl)) & 0x7FFu; // bits x-5..x+5
                unsigned vm = 0x7FFu;
                const int lo_c = 5 - x;
                if (lo_c > 0) vm &= (0x7FFu << lo_c);
                const int hi_c = x - 250;
                if (hi_c > 0) vm &= (0x7FFu >> hi_c);
                // nearest 1
                unsigned wm = win & vm;
                unsigned l = wm & 0x1Fu, r = wm >> 6;
                int dl = __clz(l) - 26;            // l==0 -> 6
                int fr = __ffs(r); int dr = fr ? fr : 6;
                const int d1 = (wm & 0x20u) ? 0 : min(dl, dr);
                // nearest 0
                wm = (~win) & vm;
                l = wm & 0x1Fu; r = wm >> 6;
                dl = __clz(l) - 26;
                fr = __ffs(r); dr = fr ? fr : 6;
                const int d0 = (wm & 0x20u) ? 0 : min(dl, dr);
                da[xl] = (float)(d1 * d1);         // 36 == "clamped >=6"
                db[xl] = (float)(d0 * d0);
            }
            va = make_float4(da[0], da[1], da[2], da[3]);
            vb = make_float4(db[0], db[1], db[2], db[3]);
        } else {
            va = make_float4(1e18f, 1e18f, 1e18f, 1e18f);
            vb = va;
        }
        *reinterpret_cast<float4*>(&sa[ry][0]) = va;
        *reinterpret_cast<float4*>(&sb[ry][0]) = vb;
    }
    __syncthreads();

    // ---------------- windowed column min-plus -----------------------------
    const int y = tid;
    float aa0 = 3.0e38f, aa1 = 3.0e38f, aa2 = 3.0e38f, aa3 = 3.0e38f;
    float ab0 = 3.0e38f, ab1 = 3.0e38f, ab2 = 3.0e38f, ab3 = 3.0e38f;
#pragma unroll
    for (int dj = -KWIN; dj <= KWIN; ++dj) {
        const float d2 = (float)(dj * dj);
        const int si = y + dj + KWIN;
        const float4 va = *reinterpret_cast<const float4*>(&sa[si][0]);
        const float4 vb = *reinterpret_cast<const float4*>(&sb[si][0]);
        aa0 = fminf(aa0, va.x + d2); aa1 = fminf(aa1, va.y + d2);
        aa2 = fminf(aa2, va.z + d2); aa3 = fminf(aa3, va.w + d2);
        ab0 = fminf(ab0, vb.x + d2); ab1 = fminf(ab1, vb.y + d2);
        ab2 = fminf(ab2, vb.z + d2); ab3 = fminf(ab3, vb.w + d2);
    }

    // Exactness: anything involving clamped row-dists or out-of-window
    // candidates exceeds (K+1)^2 = 25 -> full exact fallback for the block.
    const float thresh = (float)((KWIN + 1) * (KWIN + 1));
    const float mymax = fmaxf(fmaxf(fmaxf(aa0, aa1), fmaxf(aa2, aa3)),
                              fmaxf(fmaxf(ab0, ab1), fmaxf(ab2, ab3)));
    const int need_full = __syncthreads_or(mymax > thresh);
    if (need_full) {
        // Exact tile rebuild from bits (unclamped), then full min-plus.
        for (int ry = tid; ry < TROWS; ry += HH) {
            const int yy = ry - KWIN;
            if (yy >= 0 && yy < HH) {
                const unsigned* wr = rowbits + yy * 8;
#pragma unroll
                for (int xl = 0; xl < XT; ++xl) {
                    const int x = x0 + xl;
                    const int d1 = exact_dist(wr, x, false);
                    const int d0 = exact_dist(wr, x, true);
                    sa[ry][xl] = (d1 >= 1000) ? 1e10f : (float)(d1 * d1);
                    sb[ry][xl] = (d0 >= 1000) ? 1e10f : (float)(d0 * d0);
                }
            }
        }
        __syncthreads();
        aa0 = aa1 = aa2 = aa3 = 3.0e38f;
        ab0 = ab1 = ab2 = ab3 = 3.0e38f;
        float d = (float)y;
#pragma unroll 4
        for (int j = 0; j < HH; ++j) {
            const float d2 = d * d;
            d -= 1.0f;
            const float4 va = *reinterpret_cast<const float4*>(&sa[j + KWIN][0]);
            const float4 vb = *reinterpret_cast<const float4*>(&sb[j + KWIN][0]);
            aa0 = fminf(aa0, va.x + d2); aa1 = fminf(aa1, va.y + d2);
            aa2 = fminf(aa2, va.z + d2); aa3 = fminf(aa3, va.w + d2);
            ab0 = fminf(ab0, vb.x + d2); ab1 = fminf(ab1, vb.y + d2);
            ab2 = fminf(ab2, vb.z + d2); ab3 = fminf(ab3, vb.w + d2);
        }
    }

    // ---------------- epilogue: sigmoid + partial sums ---------------------
    const int fl = *fl_ptr;
    const int gidx = base + y * WW + x0;
    const float4 pv = *reinterpret_cast<const float4*>(&pred[gidx]);
    const float4 tv = *reinterpret_cast<const float4*>(&target[gidx]);

    float pvals[XT] = {pv.x, pv.y, pv.z, pv.w};
    float tvals[XT] = {tv.x, tv.y, tv.z, tv.w};
    float ha[XT] = {aa0, aa1, aa2, aa3};
    float hb[XT] = {ab0, ab1, ab2, ab3};

    float s_pd = 0.0f, s_pt = 0.0f, s_pp = 0.0f, s_tt = 0.0f;
#pragma unroll
    for (int k = 0; k < XT; ++k) {
        float p = pvals[k];
        if (fl) p = 1.0f / (1.0f + expf(-p));
        const float dist = sqrtf(ha[k]) + sqrtf(hb[k]);
        s_pd += p * dist;
        s_pt += p * tvals[k];
        s_pp += p * p;
        s_tt += tvals[k] * tvals[k];
    }

#pragma unroll
    for (int off = 16; off > 0; off >>= 1) {
        s_pd += __shfl_down_sync(0xffffffffu, s_pd, off);
        s_pt += __shfl_down_sync(0xffffffffu, s_pt, off);
        s_pp += __shfl_down_sync(0xffffffffu, s_pp, off);
        s_tt += __shfl_down_sync(0xffffffffu, s_tt, off);
    }
    if (lane == 0) {
        rs[warp][0] = s_pd; rs[warp][1] = s_pt;
        rs[warp][2] = s_pp; rs[warp][3] = s_tt;
    }
    __syncthreads();

    if (tid == 0) {
        double a0 = 0.0, a1 = 0.0, a2 = 0.0, a3 = 0.0;
#pragma unroll
        for (int w = 0; w < 8; ++w) {
            a0 += (double)rs[w][0]; a1 += (double)rs[w][1];
            a2 += (double)rs[w][2]; a3 += (double)rs[w][3];
        }
        d_partials[blk][0] = a0; d_partials[blk][1] = a1;
        d_partials[blk][2] = a2; d_partials[blk][3] = a3;
        __threadfence();
        const int old = atomicAdd(&g_fin, 1);
        s_last = (old == NBLK - 1);
    }
    __syncthreads();
    if (!s_last) return;

    // ---------------- last block: deterministic finalize -------------------
    __threadfence();
    {
        const int g = warp;  // one warp per image (8 warps, 8 images)
        const int s = g * 64 + lane;
        double v0 = d_partials[s][0] + d_partials[s + 32][0];
        double v1 = d_partials[s][1] + d_partials[s + 32][1];
        double v2 = d_partials[s][2] + d_partials[s + 32][2];
        double v3 = d_partials[s][3] + d_partials[s + 32][3];
#pragma unroll
        for (int off = 16; off > 0; off >>= 1) {
            v0 += __shfl_down_sync(0xffffffffu, v0, off);
            v1 += __shfl_down_sync(0xffffffffu, v1, off);
            v2 += __shfl_down_sync(0xffffffffu, v2, off);
            v3 += __shfl_down_sync(0xffffffffu, v3, off);
        }
        if (lane == 0) {
            const double eps = 1e-6;
            fg[g][0] = v0;                                        // boundary sum
            fg[g][1] = 1.0 - (2.0 * v1 + eps) / (v2 + v3 + eps);  // dice term
        }
    }
    __syncthreads();
    if (tid == 0) {
        double bl = 0.0, dl = 0.0;
#pragma unroll
        for (int g = 0; g < BB; ++g) { bl += fg[g][0]; dl += fg[g][1]; }
        dl /= (double)BB;
        bl /= (double)(BB * HH * WW);
        out[0] = (float)(dl + bl);  // ALPHA = BETA = 1
        g_bar = 0;                  // reset counters for next (graph) replay
        g_fin = 0;
        __threadfence();
    }
}

// ---------------------------------------------------------------------------
extern "C" void kernel_launch(void* const* d_in, const int* in_sizes, int n_in,
                              void* d_out, int out_size) {
    const float* pred   = (const float*)d_in[0];
    const float* target = (const float*)d_in[1];
    const int*   fl     = (const int*)d_in[2];
    float* out = (float*)d_out;

    fused<<<NBLK, HH>>>(pred, target, fl, out);
}